// round 1
// baseline (speedup 1.0000x reference)
#include <cuda_runtime.h>
#include <math_constants.h>

// Problem constants (fixed by the dataset)
#define BB 8
#define TT 2048
#define CC 1024
#define SS 256
#define KTOP 8

// ---------------- scratch (allocation-free: __device__ globals) ----------------
__device__ float g_slots[BB * SS * CC];    // 8 MB
__device__ float g_q[BB * TT * CC];        // 64 MB
__device__ float g_k[BB * SS * CC];        // 8 MB
__device__ float g_v[BB * SS * CC];        // 8 MB
__device__ float g_scores[BB * TT * SS];   // 16 MB
__device__ float g_ret[BB * TT * CC];      // 64 MB

// ---------------- pooling: slots[b,s,c] = mean over 8 timesteps ----------------
__global__ void pool_kernel(const float* __restrict__ x) {
    int i = blockIdx.x * 256 + threadIdx.x;           // i in [0, BB*SS*CC)
    int c = i & (CC - 1);
    int bs = i >> 10;                                  // CC = 1024
    int s = bs & (SS - 1);
    int b = bs >> 8;                                   // SS = 256
    const float* p = x + ((long)b * TT + (long)s * 8) * CC + c;
    float sum = 0.f;
#pragma unroll
    for (int u = 0; u < 8; u++) sum += p[(long)u * CC];
    g_slots[i] = sum * 0.125f;
}

// ---------------- SGEMM: C[m,n] = alpha * sum_k A[m,k] * B[n,k] ----------------
// A: [M,K] row-major, B: [N,K] row-major (weight layout / K-major), batched via z.
// Block tile 128x128, K-tile 8, 256 threads, 8x8 micro-tile per thread.
__global__ __launch_bounds__(256, 2)
void sgemm_tn(const float* __restrict__ A, const float* __restrict__ Bm,
              float* __restrict__ Cc, int M, int N, int K,
              long sA, long sB, long sC, float alpha) {
    __shared__ float As[8][128];
    __shared__ float Bs[8][128];

    const int bz = blockIdx.z;
    A  += (long)bz * sA;
    Bm += (long)bz * sB;
    Cc += (long)bz * sC;

    const int m0 = blockIdx.y * 128;
    const int n0 = blockIdx.x * 128;
    const int tid = threadIdx.x;

    // global-load mapping: 256 threads load 128 rows x 8 k-cols (float4 each)
    const int lm = tid >> 1;            // 0..127
    const int lk = (tid & 1) << 2;      // 0 or 4

    // compute mapping: 16x16 thread grid, 8x8 outputs each
    const int tx = tid & 15;
    const int ty = tid >> 4;

    const float* Ap = A  + (long)(m0 + lm) * K + lk;
    const float* Bp = Bm + (long)(n0 + lm) * K + lk;

    float acc[8][8];
#pragma unroll
    for (int i = 0; i < 8; i++)
#pragma unroll
        for (int j = 0; j < 8; j++) acc[i][j] = 0.f;

    for (int k0 = 0; k0 < K; k0 += 8) {
        float4 a4 = *(const float4*)(Ap + k0);
        float4 b4 = *(const float4*)(Bp + k0);
        As[lk + 0][lm] = a4.x; As[lk + 1][lm] = a4.y;
        As[lk + 2][lm] = a4.z; As[lk + 3][lm] = a4.w;
        Bs[lk + 0][lm] = b4.x; Bs[lk + 1][lm] = b4.y;
        Bs[lk + 2][lm] = b4.z; Bs[lk + 3][lm] = b4.w;
        __syncthreads();

#pragma unroll
        for (int kk = 0; kk < 8; kk++) {
            float ra[8], rb[8];
            // vectorized smem reads (2x float4 each)
            float4 ra0 = *(const float4*)&As[kk][ty * 8];
            float4 ra1 = *(const float4*)&As[kk][ty * 8 + 4];
            float4 rb0 = *(const float4*)&Bs[kk][tx * 8];
            float4 rb1 = *(const float4*)&Bs[kk][tx * 8 + 4];
            ra[0]=ra0.x; ra[1]=ra0.y; ra[2]=ra0.z; ra[3]=ra0.w;
            ra[4]=ra1.x; ra[5]=ra1.y; ra[6]=ra1.z; ra[7]=ra1.w;
            rb[0]=rb0.x; rb[1]=rb0.y; rb[2]=rb0.z; rb[3]=rb0.w;
            rb[4]=rb1.x; rb[5]=rb1.y; rb[6]=rb1.z; rb[7]=rb1.w;
#pragma unroll
            for (int i = 0; i < 8; i++)
#pragma unroll
                for (int j = 0; j < 8; j++)
                    acc[i][j] = fmaf(ra[i], rb[j], acc[i][j]);
        }
        __syncthreads();
    }

#pragma unroll
    for (int i = 0; i < 8; i++) {
        float* crow = Cc + (long)(m0 + ty * 8 + i) * N + n0 + tx * 8;
#pragma unroll
        for (int j = 0; j < 8; j += 4) {
            float4 o = make_float4(alpha * acc[i][j],     alpha * acc[i][j + 1],
                                   alpha * acc[i][j + 2], alpha * acc[i][j + 3]);
            *(float4*)(crow + j) = o;
        }
    }
}

// ------------- top-8 + softmax + weighted gather of V (one warp per (b,t)) -------------
__global__ void topk_gather_kernel() {
    const int warp_global = (blockIdx.x * blockDim.x + threadIdx.x) >> 5;   // b*T + t
    const int lane = threadIdx.x & 31;
    const int b = warp_global >> 11;           // TT = 2048
    const int t = warp_global & (TT - 1);

    const float* srow = g_scores + ((long)b * TT + t) * SS;

    float vals[8];
#pragma unroll
    for (int i = 0; i < 8; i++) vals[i] = srow[lane + 32 * i];

    float w[KTOP];
    int   idx[KTOP];

#pragma unroll
    for (int r = 0; r < KTOP; r++) {
        float best = -CUDART_INF_F;
        int   bi   = 0x7fffffff;
#pragma unroll
        for (int i = 0; i < 8; i++) {
            // ascending i => smaller slot index wins strict-compare ties within lane
            if (vals[i] > best) { best = vals[i]; bi = lane + 32 * i; }
        }
        // warp argmax reduce; ties -> smaller index (matches jax top_k)
#pragma unroll
        for (int off = 16; off; off >>= 1) {
            float ov = __shfl_xor_sync(0xffffffffu, best, off);
            int   oi = __shfl_xor_sync(0xffffffffu, bi, off);
            if (ov > best || (ov == best && oi < bi)) { best = ov; bi = oi; }
        }
        w[r] = best;
        idx[r] = bi;
        // remove selected
#pragma unroll
        for (int i = 0; i < 8; i++)
            if ((lane + 32 * i) == bi) vals[i] = -CUDART_INF_F;
    }

    // softmax over the 8 selected scores (w[0] is the max)
    float mx = w[0];
    float sum = 0.f;
#pragma unroll
    for (int r = 0; r < KTOP; r++) { w[r] = __expf(w[r] - mx); sum += w[r]; }
    float inv = 1.f / sum;
#pragma unroll
    for (int r = 0; r < KTOP; r++) w[r] *= inv;

    // retrieved[c] = sum_r w[r] * v[b, idx[r], c]
    const float* vb = g_v + (long)b * SS * CC;
    float* o = g_ret + ((long)b * TT + t) * CC;
#pragma unroll
    for (int it = 0; it < CC / 128; it++) {
        int c = lane * 4 + it * 128;
        float4 acc = make_float4(0.f, 0.f, 0.f, 0.f);
#pragma unroll
        for (int r = 0; r < KTOP; r++) {
            float4 vv = *(const float4*)(vb + (long)idx[r] * CC + c);
            acc.x = fmaf(w[r], vv.x, acc.x);
            acc.y = fmaf(w[r], vv.y, acc.y);
            acc.z = fmaf(w[r], vv.z, acc.z);
            acc.w = fmaf(w[r], vv.w, acc.w);
        }
        *(float4*)(o + c) = acc;
    }
}

// -------------------------------- launch --------------------------------
extern "C" void kernel_launch(void* const* d_in, const int* in_sizes, int n_in,
                              void* d_out, int out_size) {
    const float* x  = (const float*)d_in[0];
    const float* Wq = (const float*)d_in[1];
    const float* Wk = (const float*)d_in[2];
    const float* Wv = (const float*)d_in[3];
    const float* Wp = (const float*)d_in[4];
    float* out = (float*)d_out;

    void *p_slots, *p_q, *p_k, *p_v, *p_scores, *p_ret;
    cudaGetSymbolAddress(&p_slots,  g_slots);
    cudaGetSymbolAddress(&p_q,      g_q);
    cudaGetSymbolAddress(&p_k,      g_k);
    cudaGetSymbolAddress(&p_v,      g_v);
    cudaGetSymbolAddress(&p_scores, g_scores);
    cudaGetSymbolAddress(&p_ret,    g_ret);
    float* slots  = (float*)p_slots;
    float* q      = (float*)p_q;
    float* k      = (float*)p_k;
    float* v      = (float*)p_v;
    float* scores = (float*)p_scores;
    float* ret    = (float*)p_ret;

    // 1) pool x -> slots
    pool_kernel<<<(BB * SS * CC) / 256, 256>>>(x);

    // 2) k = slots @ Wk^T, v = slots @ Wv^T   (M = B*S = 2048)
    {
        dim3 grid(CC / 128, (BB * SS) / 128, 1);
        sgemm_tn<<<grid, 256>>>(slots, Wk, k, BB * SS, CC, CC, 0, 0, 0, 1.0f);
        sgemm_tn<<<grid, 256>>>(slots, Wv, v, BB * SS, CC, CC, 0, 0, 0, 1.0f);
    }

    // 3) q = x @ Wq^T   (M = B*T = 16384)
    {
        dim3 grid(CC / 128, (BB * TT) / 128, 1);
        sgemm_tn<<<grid, 256>>>(x, Wq, q, BB * TT, CC, CC, 0, 0, 0, 1.0f);
    }

    // 4) scores[b] = q[b] @ k[b]^T / sqrt(C)   (batched, M=T, N=S, K=C)
    {
        dim3 grid(SS / 128, TT / 128, BB);
        sgemm_tn<<<grid, 256>>>(q, k, scores, TT, SS, CC,
                                (long)TT * CC, (long)SS * CC, (long)TT * SS,
                                0.03125f /* 1/sqrt(1024) */);
    }

    // 5) top-8 + softmax + gather -> ret
    topk_gather_kernel<<<(BB * TT) / 8, 256>>>();

    // 6) out = ret @ Wp^T * 0.5
    {
        dim3 grid(CC / 128, (BB * TT) / 128, 1);
        sgemm_tn<<<grid, 256>>>(ret, Wp, out, BB * TT, CC, CC, 0, 0, 0, 0.5f);
    }
}

// round 3
// speedup vs baseline: 1.8988x; 1.8988x over previous
#include <cuda_runtime.h>
#include <cuda_bf16.h>
#include <math_constants.h>
#include <cstdint>

// Problem constants
#define BB 8
#define TT 2048
#define CC 1024
#define SS 256
#define KTOP 8

// ---------------------------------------------------------------------------
// bf16 hi/lo split helpers
// ---------------------------------------------------------------------------
__device__ __forceinline__ uint32_t pack_bf2(float a, float b) {
    __nv_bfloat162 h = __float22bfloat162_rn(make_float2(a, b));
    return *reinterpret_cast<uint32_t*>(&h);
}
__device__ __forceinline__ float2 unpack_bf2(uint32_t u) {
    __nv_bfloat162 h = *reinterpret_cast<__nv_bfloat162*>(&u);
    return __bfloat1622float2(h);
}

// m16n8k16 bf16 HMMA (baseline PTX path — works on plain sm_103 target)
__device__ __forceinline__ void mma_bf16(float* d, const uint32_t* a, const uint32_t* b) {
    asm volatile(
        "mma.sync.aligned.m16n8k16.row.col.f32.bf16.bf16.f32 "
        "{%0,%1,%2,%3}, {%4,%5,%6,%7}, {%8,%9}, {%0,%1,%2,%3};"
        : "+f"(d[0]), "+f"(d[1]), "+f"(d[2]), "+f"(d[3])
        : "r"(a[0]), "r"(a[1]), "r"(a[2]), "r"(a[3]), "r"(b[0]), "r"(b[1]));
}

// ---------------------------------------------------------------------------
// scratch (__device__ globals; allocation-free)
// ---------------------------------------------------------------------------
__device__ __nv_bfloat16 g_xh[BB * TT * CC];
__device__ __nv_bfloat16 g_xl[BB * TT * CC];
__device__ __nv_bfloat16 g_qh[BB * TT * CC];
__device__ __nv_bfloat16 g_ql[BB * TT * CC];
__device__ __nv_bfloat16 g_rh[BB * TT * CC];
__device__ __nv_bfloat16 g_rl[BB * TT * CC];
__device__ __nv_bfloat16 g_sh[BB * SS * CC];
__device__ __nv_bfloat16 g_sl[BB * SS * CC];
__device__ __nv_bfloat16 g_kh[BB * SS * CC];
__device__ __nv_bfloat16 g_kl[BB * SS * CC];
__device__ float         g_v [BB * SS * CC];
__device__ float         g_scores[BB * TT * SS];
__device__ __nv_bfloat16 g_wh[4 * CC * CC];
__device__ __nv_bfloat16 g_wl[4 * CC * CC];

// ---------------------------------------------------------------------------
// fp32 -> bf16 hi/lo conversion
// ---------------------------------------------------------------------------
__global__ void cvt_hilo(const float4* __restrict__ in, uint2* __restrict__ hi,
                         uint2* __restrict__ lo, int n4) {
    int i = blockIdx.x * 256 + threadIdx.x;
    if (i >= n4) return;
    float4 f = in[i];
    uint32_t h0 = pack_bf2(f.x, f.y);
    uint32_t h1 = pack_bf2(f.z, f.w);
    float2 e0 = unpack_bf2(h0), e1 = unpack_bf2(h1);
    uint32_t l0 = pack_bf2(f.x - e0.x, f.y - e0.y);
    uint32_t l1 = pack_bf2(f.z - e1.x, f.w - e1.y);
    hi[i] = make_uint2(h0, h1);
    lo[i] = make_uint2(l0, l1);
}

// ---------------------------------------------------------------------------
// pooling: slots = mean over 8 timesteps -> bf16 hi/lo
// ---------------------------------------------------------------------------
__global__ void pool_kernel(const float* __restrict__ x) {
    int i = blockIdx.x * 256 + threadIdx.x;
    int c = i & (CC - 1);
    int bs = i >> 10;
    int s = bs & (SS - 1);
    int b = bs >> 8;
    const float* p = x + ((long)b * TT + (long)s * 8) * CC + c;
    float sum = 0.f;
#pragma unroll
    for (int u = 0; u < 8; u++) sum += p[(long)u * CC];
    sum *= 0.125f;
    __nv_bfloat16 h = __float2bfloat16_rn(sum);
    g_sh[i] = h;
    g_sl[i] = __float2bfloat16_rn(sum - __bfloat162float(h));
}

// ---------------------------------------------------------------------------
// HMMA split-bf16 GEMM: C[m,n] = alpha * sum_k (Ah+Al)[m,k]*(Bh+Bl)[n,k]
//   3 products: AhBh + AhBl + AlBh, fp32 accumulate.
// BM=BN=128, BK=32, 256 threads, 8 warps (2m x 4n), warp tile 64x32.
// SMEM holds pre-arranged mma fragments; double buffered (2 x 32KB).
//   A tile per stage: [kstep(2)][mfrag(8)][lane(32)][reg(4)] u32  = 8KB
//   B tile per stage: [kstep(2)][nfrag(16)][lane(32)][reg(2)] u32 = 8KB
// mode 0: fp32 out Cf;  mode 1: bf16 hi/lo out Chi/Clo.
// ---------------------------------------------------------------------------
#define GEMM_SMEM (2 * 32768)

__global__ __launch_bounds__(256, 1)
void gemm_mma(const __nv_bfloat16* __restrict__ Ah, const __nv_bfloat16* __restrict__ Al,
              const __nv_bfloat16* __restrict__ Bh, const __nv_bfloat16* __restrict__ Bl,
              float* __restrict__ Cf, __nv_bfloat16* __restrict__ Chi, __nv_bfloat16* __restrict__ Clo,
              int M, int N, int K,
              long long sA, long long sB, long long sC, float alpha, int mode) {
    extern __shared__ __align__(16) char smem[];

    const int tid = threadIdx.x;
    const int wid = tid >> 5;
    const int lane = tid & 31;
    const int bz = blockIdx.z;
    const size_t m0 = (size_t)blockIdx.y * 128;
    const size_t n0 = (size_t)blockIdx.x * 128;

    // ---- loader mapping: thread -> (row, k-half of 16) ----
    const int lrow = tid >> 1;
    const int khalf = tid & 1;
    const __nv_bfloat16* gAh = Ah + (size_t)bz * (size_t)sA + (m0 + lrow) * (size_t)K + khalf * 16;
    const __nv_bfloat16* gAl = Al + (size_t)bz * (size_t)sA + (m0 + lrow) * (size_t)K + khalf * 16;
    const __nv_bfloat16* gBh = Bh + (size_t)bz * (size_t)sB + (n0 + lrow) * (size_t)K + khalf * 16;
    const __nv_bfloat16* gBl = Bl + (size_t)bz * (size_t)sB + (n0 + lrow) * (size_t)K + khalf * 16;

    // fragment-store offsets for this thread's 8 u32 (16 bf16)
    const int ablk = (khalf * 8 + (lrow >> 4)) * 512;   // A block byte offset
    const int g4   = (lrow & 7) * 4;
    const int rb   = (lrow >> 3) & 1;
    const int bblk = (khalf * 16 + (lrow >> 3)) * 256;  // B block byte offset
    const int gb4  = (lrow & 7) * 4;

    // ---- compute mapping ----
    const int wm = wid >> 2;   // 0..1 : 64-row half
    const int wn = wid & 3;    // 0..3 : 32-col quarter

    float acc[4][4][4];
#pragma unroll
    for (int i = 0; i < 4; i++)
#pragma unroll
        for (int j = 0; j < 4; j++)
#pragma unroll
            for (int r = 0; r < 4; r++) acc[i][j][r] = 0.f;

    const int nch = K >> 5;    // chunks of BK=32
    uint4 rAh[2], rAl[2], rBh[2], rBl[2];

#define LDG_CHUNK(c) do { \
    const uint4* pa = (const uint4*)(gAh + (c) * 32); rAh[0] = pa[0]; rAh[1] = pa[1]; \
    const uint4* pb = (const uint4*)(gAl + (c) * 32); rAl[0] = pb[0]; rAl[1] = pb[1]; \
    const uint4* pc = (const uint4*)(gBh + (c) * 32); rBh[0] = pc[0]; rBh[1] = pc[1]; \
    const uint4* pd = (const uint4*)(gBl + (c) * 32); rBl[0] = pd[0]; rBl[1] = pd[1]; \
} while (0)

#define STS_CHUNK(stg) do { \
    char* st = smem + (stg) * 32768; \
    const uint32_t* ah32 = (const uint32_t*)rAh; \
    const uint32_t* al32 = (const uint32_t*)rAl; \
    const uint32_t* bh32 = (const uint32_t*)rBh; \
    const uint32_t* bl32 = (const uint32_t*)rBl; \
    _Pragma("unroll") \
    for (int j = 0; j < 8; j++) { \
        int aoff = ablk + ((g4 + (j & 3)) << 4) + ((rb + 2 * (j >> 2)) << 2); \
        int boff = bblk + ((gb4 + (j & 3)) << 3) + ((j >> 2) << 2); \
        *(uint32_t*)(st + aoff)         = ah32[j]; \
        *(uint32_t*)(st + 8192 + aoff)  = al32[j]; \
        *(uint32_t*)(st + 16384 + boff) = bh32[j]; \
        *(uint32_t*)(st + 24576 + boff) = bl32[j]; \
    } \
} while (0)

    // prologue
    LDG_CHUNK(0);
    STS_CHUNK(0);
    __syncthreads();

    for (int c = 0; c < nch; c++) {
        if (c + 1 < nch) LDG_CHUNK(c + 1);

        // compute from stage c&1
        {
            char* st = smem + (c & 1) * 32768;
#pragma unroll
            for (int ks = 0; ks < 2; ks++) {
                uint2 bh[4], bl[4];
#pragma unroll
                for (int fn = 0; fn < 4; fn++) {
                    int boff = ((ks * 16 + wn * 4 + fn) * 32 + lane) * 8;
                    bh[fn] = *(const uint2*)(st + 16384 + boff);
                    bl[fn] = *(const uint2*)(st + 24576 + boff);
                }
#pragma unroll
                for (int fm = 0; fm < 4; fm++) {
                    int aoff = ((ks * 8 + wm * 4 + fm) * 32 + lane) * 16;
                    uint4 ah = *(const uint4*)(st + aoff);
                    uint4 al = *(const uint4*)(st + 8192 + aoff);
#pragma unroll
                    for (int fn = 0; fn < 4; fn++)
                        mma_bf16(acc[fm][fn], (const uint32_t*)&ah, (const uint32_t*)&bh[fn]);
#pragma unroll
                    for (int fn = 0; fn < 4; fn++)
                        mma_bf16(acc[fm][fn], (const uint32_t*)&ah, (const uint32_t*)&bl[fn]);
#pragma unroll
                    for (int fn = 0; fn < 4; fn++)
                        mma_bf16(acc[fm][fn], (const uint32_t*)&al, (const uint32_t*)&bh[fn]);
                }
            }
        }

        if (c + 1 < nch) STS_CHUNK((c + 1) & 1);
        __syncthreads();
    }

    // ---- epilogue ----
    const int eg = lane >> 2;          // row within frag (0..7)
    const int et = lane & 3;           // col pair (0..3)
    const size_t cbase = (size_t)bz * (size_t)sC;

#pragma unroll
    for (int fm = 0; fm < 4; fm++) {
        size_t row0 = m0 + (wm * 4 + fm) * 16 + eg;
#pragma unroll
        for (int fn = 0; fn < 4; fn++) {
            size_t col = n0 + (wn * 4 + fn) * 8 + et * 2;
            float c0 = alpha * acc[fm][fn][0];
            float c1 = alpha * acc[fm][fn][1];
            float c2 = alpha * acc[fm][fn][2];
            float c3 = alpha * acc[fm][fn][3];
            if (mode == 0) {
                *(float2*)(Cf + cbase + row0 * N + col)       = make_float2(c0, c1);
                *(float2*)(Cf + cbase + (row0 + 8) * N + col) = make_float2(c2, c3);
            } else {
                uint32_t h0 = pack_bf2(c0, c1);
                float2 e0 = unpack_bf2(h0);
                uint32_t l0 = pack_bf2(c0 - e0.x, c1 - e0.y);
                uint32_t h1 = pack_bf2(c2, c3);
                float2 e1 = unpack_bf2(h1);
                uint32_t l1 = pack_bf2(c2 - e1.x, c3 - e1.y);
                *(uint32_t*)(Chi + cbase + row0 * N + col)       = h0;
                *(uint32_t*)(Clo + cbase + row0 * N + col)       = l0;
                *(uint32_t*)(Chi + cbase + (row0 + 8) * N + col) = h1;
                *(uint32_t*)(Clo + cbase + (row0 + 8) * N + col) = l1;
            }
        }
    }
#undef LDG_CHUNK
#undef STS_CHUNK
}

// ---------------------------------------------------------------------------
// top-8 + softmax + weighted V gather (one warp per (b,t)); writes ret hi/lo
// ---------------------------------------------------------------------------
__global__ void topk_gather_kernel() {
    const int warp_global = (blockIdx.x * blockDim.x + threadIdx.x) >> 5;
    const int lane = threadIdx.x & 31;
    const int b = warp_global >> 11;
    const int t = warp_global & (TT - 1);

    const float* srow = g_scores + ((long)b * TT + t) * SS;

    float vals[8];
#pragma unroll
    for (int i = 0; i < 8; i++) vals[i] = srow[lane + 32 * i];

    float w[KTOP];
    int   idx[KTOP];

#pragma unroll
    for (int r = 0; r < KTOP; r++) {
        float best = -CUDART_INF_F;
        int   bi = 0x7fffffff;
#pragma unroll
        for (int i = 0; i < 8; i++)
            if (vals[i] > best) { best = vals[i]; bi = lane + 32 * i; }
#pragma unroll
        for (int off = 16; off; off >>= 1) {
            float ov = __shfl_xor_sync(0xffffffffu, best, off);
            int   oi = __shfl_xor_sync(0xffffffffu, bi, off);
            if (ov > best || (ov == best && oi < bi)) { best = ov; bi = oi; }
        }
        w[r] = best;
        idx[r] = bi;
#pragma unroll
        for (int i = 0; i < 8; i++)
            if ((lane + 32 * i) == bi) vals[i] = -CUDART_INF_F;
    }

    float mx = w[0];
    float sum = 0.f;
#pragma unroll
    for (int r = 0; r < KTOP; r++) { w[r] = __expf(w[r] - mx); sum += w[r]; }
    float inv = 1.f / sum;
#pragma unroll
    for (int r = 0; r < KTOP; r++) w[r] *= inv;

    const float* vb = g_v + (long)b * SS * CC;
    const long ro = ((long)b * TT + t) * CC;
#pragma unroll
    for (int it = 0; it < CC / 128; it++) {
        int c = lane * 4 + it * 128;
        float4 acc = make_float4(0.f, 0.f, 0.f, 0.f);
#pragma unroll
        for (int r = 0; r < KTOP; r++) {
            float4 vv = *(const float4*)(vb + (long)idx[r] * CC + c);
            acc.x = fmaf(w[r], vv.x, acc.x);
            acc.y = fmaf(w[r], vv.y, acc.y);
            acc.z = fmaf(w[r], vv.z, acc.z);
            acc.w = fmaf(w[r], vv.w, acc.w);
        }
        uint32_t h0 = pack_bf2(acc.x, acc.y), h1 = pack_bf2(acc.z, acc.w);
        float2 e0 = unpack_bf2(h0), e1 = unpack_bf2(h1);
        uint32_t l0 = pack_bf2(acc.x - e0.x, acc.y - e0.y);
        uint32_t l1 = pack_bf2(acc.z - e1.x, acc.w - e1.y);
        *(uint2*)(g_rh + ro + c) = make_uint2(h0, h1);
        *(uint2*)(g_rl + ro + c) = make_uint2(l0, l1);
    }
}

// ---------------------------------------------------------------------------
// launch
// ---------------------------------------------------------------------------
extern "C" void kernel_launch(void* const* d_in, const int* in_sizes, int n_in,
                              void* d_out, int out_size) {
    const float* x  = (const float*)d_in[0];
    const float* Wq = (const float*)d_in[1];
    const float* Wk = (const float*)d_in[2];
    const float* Wv = (const float*)d_in[3];
    const float* Wp = (const float*)d_in[4];
    float* out = (float*)d_out;

    void *pxh, *pxl, *pqh, *pql, *prh, *prl, *psh, *psl, *pkh, *pkl, *pv, *psc, *pwh, *pwl;
    cudaGetSymbolAddress(&pxh, g_xh); cudaGetSymbolAddress(&pxl, g_xl);
    cudaGetSymbolAddress(&pqh, g_qh); cudaGetSymbolAddress(&pql, g_ql);
    cudaGetSymbolAddress(&prh, g_rh); cudaGetSymbolAddress(&prl, g_rl);
    cudaGetSymbolAddress(&psh, g_sh); cudaGetSymbolAddress(&psl, g_sl);
    cudaGetSymbolAddress(&pkh, g_kh); cudaGetSymbolAddress(&pkl, g_kl);
    cudaGetSymbolAddress(&pv, g_v);   cudaGetSymbolAddress(&psc, g_scores);
    cudaGetSymbolAddress(&pwh, g_wh); cudaGetSymbolAddress(&pwl, g_wl);

    __nv_bfloat16* xh = (__nv_bfloat16*)pxh; __nv_bfloat16* xl = (__nv_bfloat16*)pxl;
    __nv_bfloat16* qh = (__nv_bfloat16*)pqh; __nv_bfloat16* ql = (__nv_bfloat16*)pql;
    __nv_bfloat16* rh = (__nv_bfloat16*)prh; __nv_bfloat16* rl = (__nv_bfloat16*)prl;
    __nv_bfloat16* sh = (__nv_bfloat16*)psh; __nv_bfloat16* sl = (__nv_bfloat16*)psl;
    __nv_bfloat16* kh = (__nv_bfloat16*)pkh; __nv_bfloat16* kl = (__nv_bfloat16*)pkl;
    float* v = (float*)pv; float* scores = (float*)psc;
    __nv_bfloat16* wh = (__nv_bfloat16*)pwh; __nv_bfloat16* wl = (__nv_bfloat16*)pwl;

    cudaFuncSetAttribute(gemm_mma, cudaFuncAttributeMaxDynamicSharedMemorySize, GEMM_SMEM);

    // 1) convert x and weights to hi/lo bf16
    {
        int n4 = BB * TT * CC / 4;
        cvt_hilo<<<(n4 + 255) / 256, 256>>>((const float4*)x, (uint2*)xh, (uint2*)xl, n4);
        int w4 = CC * CC / 4;
        cvt_hilo<<<(w4 + 255) / 256, 256>>>((const float4*)Wq, (uint2*)(wh + 0 * CC * CC), (uint2*)(wl + 0 * CC * CC), w4);
        cvt_hilo<<<(w4 + 255) / 256, 256>>>((const float4*)Wk, (uint2*)(wh + 1 * CC * CC), (uint2*)(wl + 1 * CC * CC), w4);
        cvt_hilo<<<(w4 + 255) / 256, 256>>>((const float4*)Wv, (uint2*)(wh + 2 * CC * CC), (uint2*)(wl + 2 * CC * CC), w4);
        cvt_hilo<<<(w4 + 255) / 256, 256>>>((const float4*)Wp, (uint2*)(wh + 3 * CC * CC), (uint2*)(wl + 3 * CC * CC), w4);
    }

    // 2) pool x -> slots hi/lo
    pool_kernel<<<(BB * SS * CC) / 256, 256>>>(x);

    // 3) k = slots @ Wk^T (hi/lo out), v = slots @ Wv^T (fp32 out)
    {
        dim3 grid(CC / 128, (BB * SS) / 128, 1);
        gemm_mma<<<grid, 256, GEMM_SMEM>>>(sh, sl, wh + 1 * CC * CC, wl + 1 * CC * CC,
                                           nullptr, kh, kl, BB * SS, CC, CC, 0, 0, 0, 1.0f, 1);
        gemm_mma<<<grid, 256, GEMM_SMEM>>>(sh, sl, wh + 2 * CC * CC, wl + 2 * CC * CC,
                                           v, nullptr, nullptr, BB * SS, CC, CC, 0, 0, 0, 1.0f, 0);
    }

    // 4) q = x @ Wq^T (hi/lo out)
    {
        dim3 grid(CC / 128, (BB * TT) / 128, 1);
        gemm_mma<<<grid, 256, GEMM_SMEM>>>(xh, xl, wh + 0 * CC * CC, wl + 0 * CC * CC,
                                           nullptr, qh, ql, BB * TT, CC, CC, 0, 0, 0, 1.0f, 1);
    }

    // 5) scores[b] = q[b] @ k[b]^T / 32 (batched, fp32 out)
    {
        dim3 grid(SS / 128, TT / 128, BB);
        gemm_mma<<<grid, 256, GEMM_SMEM>>>(qh, ql, kh, kl, scores, nullptr, nullptr,
                                           TT, SS, CC,
                                           (long long)TT * CC, (long long)SS * CC, (long long)TT * SS,
                                           0.03125f, 0);
    }

    // 6) top-8 + softmax + gather -> ret hi/lo
    topk_gather_kernel<<<(BB * TT) / 8, 256>>>();

    // 7) out = ret @ Wp^T * 0.5 (fp32 out)
    {
        dim3 grid(CC / 128, (BB * TT) / 128, 1);
        gemm_mma<<<grid, 256, GEMM_SMEM>>>(rh, rl, wh + 3 * CC * CC, wl + 3 * CC * CC,
                                           out, nullptr, nullptr, BB * TT, CC, CC, 0, 0, 0, 0.5f, 0);
    }
}

// round 5
// speedup vs baseline: 2.0865x; 1.0988x over previous
#include <cuda_runtime.h>
#include <cuda_bf16.h>
#include <math_constants.h>
#include <cstdint>

#define BB 8
#define TT 2048
#define CC 1024
#define SS 256
#define KTOP 8

// ---------------------------------------------------------------------------
// helpers
// ---------------------------------------------------------------------------
__device__ __forceinline__ uint32_t smem_u32(const void* p) {
    uint32_t a;
    asm("{ .reg .u64 t; cvta.to.shared.u64 t, %1; cvt.u32.u64 %0, t; }" : "=r"(a) : "l"(p));
    return a;
}
__device__ __forceinline__ uint32_t pack_bf2(float a, float b) {
    __nv_bfloat162 h = __float22bfloat162_rn(make_float2(a, b));
    return *reinterpret_cast<uint32_t*>(&h);
}
__device__ __forceinline__ float2 unpack_bf2(uint32_t u) {
    __nv_bfloat162 h = *reinterpret_cast<__nv_bfloat162*>(&u);
    return __bfloat1622float2(h);
}
__device__ __forceinline__ void mma_bf16(float* d, const uint32_t* a, const uint32_t* b) {
    asm volatile(
        "mma.sync.aligned.m16n8k16.row.col.f32.bf16.bf16.f32 "
        "{%0,%1,%2,%3}, {%4,%5,%6,%7}, {%8,%9}, {%0,%1,%2,%3};"
        : "+f"(d[0]), "+f"(d[1]), "+f"(d[2]), "+f"(d[3])
        : "r"(a[0]), "r"(a[1]), "r"(a[2]), "r"(a[3]), "r"(b[0]), "r"(b[1]));
}
__device__ __forceinline__ void ldsm_x4(uint32_t* r, uint32_t addr) {
    asm volatile("ldmatrix.sync.aligned.m8n8.x4.shared.b16 {%0,%1,%2,%3}, [%4];"
        : "=r"(r[0]), "=r"(r[1]), "=r"(r[2]), "=r"(r[3]) : "r"(addr));
}
__device__ __forceinline__ void ldsm_x2(uint32_t* r, uint32_t addr) {
    asm volatile("ldmatrix.sync.aligned.m8n8.x2.shared.b16 {%0,%1}, [%2];"
        : "=r"(r[0]), "=r"(r[1]) : "r"(addr));
}
__device__ __forceinline__ void cp16(uint32_t saddr, const void* gaddr) {
    asm volatile("cp.async.cg.shared.global [%0], [%1], 16;" :: "r"(saddr), "l"(gaddr));
}

// swizzled byte offset within a tile region: row (64B pitch), 16B unit u (0..3)
__device__ __forceinline__ uint32_t swz(int row, int u) {
    return (uint32_t)(row * 64 + ((u ^ ((row >> 1) & 3)) << 4));
}

// ---------------------------------------------------------------------------
// scratch
// ---------------------------------------------------------------------------
__device__ __nv_bfloat16 g_xh[BB * TT * CC];
__device__ __nv_bfloat16 g_xl[BB * TT * CC];
__device__ __nv_bfloat16 g_qh[BB * TT * CC];
__device__ __nv_bfloat16 g_ql[BB * TT * CC];
__device__ __nv_bfloat16 g_rh[BB * TT * CC];
__device__ __nv_bfloat16 g_rl[BB * TT * CC];
__device__ __nv_bfloat16 g_sh[BB * SS * CC];
__device__ __nv_bfloat16 g_sl[BB * SS * CC];
__device__ __nv_bfloat16 g_kh[BB * SS * CC];
__device__ __nv_bfloat16 g_kl[BB * SS * CC];
__device__ float         g_v [BB * SS * CC];
__device__ float         g_scores[BB * TT * SS];
__device__ __nv_bfloat16 g_wh[4 * CC * CC];
__device__ __nv_bfloat16 g_wl[4 * CC * CC];

// ---------------------------------------------------------------------------
// fp32 -> bf16 hi/lo conversion
// ---------------------------------------------------------------------------
__global__ void cvt_hilo(const float4* __restrict__ in, uint2* __restrict__ hi,
                         uint2* __restrict__ lo, int n4) {
    int i = blockIdx.x * 256 + threadIdx.x;
    if (i >= n4) return;
    float4 f = in[i];
    uint32_t h0 = pack_bf2(f.x, f.y);
    uint32_t h1 = pack_bf2(f.z, f.w);
    float2 e0 = unpack_bf2(h0), e1 = unpack_bf2(h1);
    hi[i] = make_uint2(h0, h1);
    lo[i] = make_uint2(pack_bf2(f.x - e0.x, f.y - e0.y), pack_bf2(f.z - e1.x, f.w - e1.y));
}

// ---------------------------------------------------------------------------
// pooling -> slots hi/lo
// ---------------------------------------------------------------------------
__global__ void pool_kernel(const float* __restrict__ x) {
    int i = blockIdx.x * 256 + threadIdx.x;
    int c = i & (CC - 1);
    int bs = i >> 10;
    int s = bs & (SS - 1);
    int b = bs >> 8;
    const float* p = x + ((long)b * TT + (long)s * 8) * CC + c;
    float sum = 0.f;
#pragma unroll
    for (int u = 0; u < 8; u++) sum += p[(long)u * CC];
    sum *= 0.125f;
    __nv_bfloat16 h = __float2bfloat16_rn(sum);
    g_sh[i] = h;
    g_sl[i] = __float2bfloat16_rn(sum - __bfloat162float(h));
}

// ---------------------------------------------------------------------------
// Pipelined split-bf16 HMMA GEMM.
// C[m,n] = alpha * sum_k (Ah+Al)[m,k]*(Bh+Bl)[n,k]  (AhBh + AhBl + AlBh)
// CTA tile 128x256, BK=32, 256 threads = 8 warps (2m x 4n), warp tile 64x64.
// 3-stage cp.async pipeline; stage = [Ah 8K][Al 8K][Bh 16K][Bl 16K] = 48KB.
// mode 0: fp32 out. mode 1: bf16 hi/lo out. mode 2: kv-fuse (z=0 hi/lo, z=1 fp32).
// ---------------------------------------------------------------------------
#define STAGES 3
#define STAGE_BYTES 49152
#define GEMM_SMEM (STAGES * STAGE_BYTES)

__global__ __launch_bounds__(256, 1)
void gemm_mma(const __nv_bfloat16* __restrict__ Ah, const __nv_bfloat16* __restrict__ Al,
              const __nv_bfloat16* __restrict__ Bh, const __nv_bfloat16* __restrict__ Bl,
              float* __restrict__ Cf, __nv_bfloat16* __restrict__ Chi, __nv_bfloat16* __restrict__ Clo,
              int M, int N, int K,
              long long sA, long long sB, long long sC, float alpha, int mode) {
    extern __shared__ __align__(16) char smem[];
    const uint32_t sb = smem_u32(smem);

    const int tid = threadIdx.x;
    const int wid = tid >> 5;
    const int lane = tid & 31;
    const int bz = blockIdx.z;
    const size_t m0 = (size_t)blockIdx.y * 128;
    const size_t n0 = (size_t)blockIdx.x * 256;

    const __nv_bfloat16* gAh = Ah + (size_t)bz * (size_t)sA;
    const __nv_bfloat16* gAl = Al + (size_t)bz * (size_t)sA;
    const __nv_bfloat16* gBh = Bh + (size_t)bz * (size_t)sB;
    const __nv_bfloat16* gBl = Bl + (size_t)bz * (size_t)sB;

    // loader mapping
    const int arow = tid >> 1;               // 0..127
    const int au   = (tid & 1) * 2;          // 0 or 2
    const int brow = tid;                    // 0..255
    const size_t aoffg = (m0 + arow) * (size_t)K;   // + c*32 + u*8
    const size_t boffg = (n0 + brow) * (size_t)K;

    const int nch = K >> 5;

#define LOAD_STAGE(stg) do { \
    const uint32_t st = sb + ((stg) % STAGES) * STAGE_BYTES; \
    const int kof = (stg) * 32; \
    _Pragma("unroll") \
    for (int j = 0; j < 2; j++) { \
        int u = au + j; \
        uint32_t so = swz(arow, u); \
        size_t go = aoffg + kof + u * 8; \
        cp16(st + so,        gAh + go); \
        cp16(st + 8192 + so, gAl + go); \
    } \
    _Pragma("unroll") \
    for (int u = 0; u < 4; u++) { \
        uint32_t so = swz(brow, u); \
        size_t go = boffg + kof + u * 8; \
        cp16(st + 16384 + so, gBh + go); \
        cp16(st + 32768 + so, gBl + go); \
    } \
} while (0)

    // compute mapping
    const int wm = wid >> 2;     // 0..1
    const int wn = wid & 3;      // 0..3

    float acc[4][8][4];
#pragma unroll
    for (int i = 0; i < 4; i++)
#pragma unroll
        for (int j = 0; j < 8; j++)
#pragma unroll
            for (int r = 0; r < 4; r++) acc[i][j][r] = 0.f;

    // prologue: issue first STAGES-1 stages
#pragma unroll
    for (int s = 0; s < STAGES - 1; s++) {
        if (s < nch) LOAD_STAGE(s);
        asm volatile("cp.async.commit_group;" ::: "memory");
    }

    for (int c = 0; c < nch; c++) {
        asm volatile("cp.async.wait_group %0;" :: "n"(STAGES - 2) : "memory");
        __syncthreads();

        if (c + STAGES - 1 < nch) LOAD_STAGE(c + STAGES - 1);
        asm volatile("cp.async.commit_group;" ::: "memory");

        const uint32_t st = sb + (c % STAGES) * STAGE_BYTES;
#pragma unroll
        for (int ks = 0; ks < 2; ks++) {
            uint32_t bhf[8][2], blf[8][2];
            const int rB0 = wn * 64 + (lane & 7);
            const int cuB = 2 * ks + ((lane >> 3) & 1);
#pragma unroll
            for (int fn = 0; fn < 8; fn++) {
                int row = rB0 + 8 * fn;
                uint32_t ad = st + 16384 + swz(row, cuB);
                ldsm_x2(bhf[fn], ad);
                ldsm_x2(blf[fn], ad + 16384);
            }
#pragma unroll
            for (int fm = 0; fm < 4; fm++) {
                int rowA = wm * 64 + fm * 16 + (lane & 7) + ((lane >> 3) & 1) * 8;
                int cuA = 2 * ks + (lane >> 4);
                uint32_t ad = st + swz(rowA, cuA);
                uint32_t ah[4], al[4];
                ldsm_x4(ah, ad);
                ldsm_x4(al, ad + 8192);
#pragma unroll
                for (int fn = 0; fn < 8; fn++) mma_bf16(acc[fm][fn], ah, bhf[fn]);
#pragma unroll
                for (int fn = 0; fn < 8; fn++) mma_bf16(acc[fm][fn], ah, blf[fn]);
#pragma unroll
                for (int fn = 0; fn < 8; fn++) mma_bf16(acc[fm][fn], al, bhf[fn]);
            }
        }
    }
#undef LOAD_STAGE

    // ---- epilogue ----
    int emode = mode;
    if (mode == 2) emode = (bz == 0) ? 1 : 0;
    const size_t cbase = (mode == 2) ? 0 : (size_t)bz * (size_t)sC;
    const int eg = lane >> 2;
    const int et = lane & 3;

#pragma unroll
    for (int fm = 0; fm < 4; fm++) {
        size_t row0 = m0 + wm * 64 + fm * 16 + eg;
#pragma unroll
        for (int fn = 0; fn < 8; fn++) {
            size_t col = n0 + wn * 64 + fn * 8 + et * 2;
            float c0 = alpha * acc[fm][fn][0];
            float c1 = alpha * acc[fm][fn][1];
            float c2 = alpha * acc[fm][fn][2];
            float c3 = alpha * acc[fm][fn][3];
            if (emode == 0) {
                *(float2*)(Cf + cbase + row0 * N + col)       = make_float2(c0, c1);
                *(float2*)(Cf + cbase + (row0 + 8) * N + col) = make_float2(c2, c3);
            } else {
                uint32_t h0 = pack_bf2(c0, c1);
                float2 e0 = unpack_bf2(h0);
                uint32_t l0 = pack_bf2(c0 - e0.x, c1 - e0.y);
                uint32_t h1 = pack_bf2(c2, c3);
                float2 e1 = unpack_bf2(h1);
                uint32_t l1 = pack_bf2(c2 - e1.x, c3 - e1.y);
                *(uint32_t*)(Chi + cbase + row0 * N + col)       = h0;
                *(uint32_t*)(Clo + cbase + row0 * N + col)       = l0;
                *(uint32_t*)(Chi + cbase + (row0 + 8) * N + col) = h1;
                *(uint32_t*)(Clo + cbase + (row0 + 8) * N + col) = l1;
            }
        }
    }
}

// ---------------------------------------------------------------------------
// top-8 + softmax + weighted V gather; writes ret hi/lo
// ---------------------------------------------------------------------------
__global__ void topk_gather_kernel() {
    const int warp_global = (blockIdx.x * blockDim.x + threadIdx.x) >> 5;
    const int lane = threadIdx.x & 31;
    const int b = warp_global >> 11;
    const int t = warp_global & (TT - 1);

    const float* srow = g_scores + ((long)b * TT + t) * SS;

    float vals[8];
#pragma unroll
    for (int i = 0; i < 8; i++) vals[i] = srow[lane + 32 * i];

    float w[KTOP];
    int   idx[KTOP];

#pragma unroll
    for (int r = 0; r < KTOP; r++) {
        float best = -CUDART_INF_F;
        int   bi = 0x7fffffff;
#pragma unroll
        for (int i = 0; i < 8; i++)
            if (vals[i] > best) { best = vals[i]; bi = lane + 32 * i; }
#pragma unroll
        for (int off = 16; off; off >>= 1) {
            float ov = __shfl_xor_sync(0xffffffffu, best, off);
            int   oi = __shfl_xor_sync(0xffffffffu, bi, off);
            if (ov > best || (ov == best && oi < bi)) { best = ov; bi = oi; }
        }
        w[r] = best;
        idx[r] = bi;
#pragma unroll
        for (int i = 0; i < 8; i++)
            if ((lane + 32 * i) == bi) vals[i] = -CUDART_INF_F;
    }

    float mx = w[0];
    float sum = 0.f;
#pragma unroll
    for (int r = 0; r < KTOP; r++) { w[r] = __expf(w[r] - mx); sum += w[r]; }
    float inv = 1.f / sum;
#pragma unroll
    for (int r = 0; r < KTOP; r++) w[r] *= inv;

    const float* vb = g_v + (long)b * SS * CC;
    const long ro = ((long)b * TT + t) * CC;
#pragma unroll
    for (int it = 0; it < CC / 128; it++) {
        int c = lane * 4 + it * 128;
        float4 acc = make_float4(0.f, 0.f, 0.f, 0.f);
#pragma unroll
        for (int r = 0; r < KTOP; r++) {
            float4 vv = *(const float4*)(vb + (long)idx[r] * CC + c);
            acc.x = fmaf(w[r], vv.x, acc.x);
            acc.y = fmaf(w[r], vv.y, acc.y);
            acc.z = fmaf(w[r], vv.z, acc.z);
            acc.w = fmaf(w[r], vv.w, acc.w);
        }
        uint32_t h0 = pack_bf2(acc.x, acc.y), h1 = pack_bf2(acc.z, acc.w);
        float2 e0 = unpack_bf2(h0), e1 = unpack_bf2(h1);
        *(uint2*)(g_rh + ro + c) = make_uint2(h0, h1);
        *(uint2*)(g_rl + ro + c) = make_uint2(pack_bf2(acc.x - e0.x, acc.y - e0.y),
                                              pack_bf2(acc.z - e1.x, acc.w - e1.y));
    }
}

// ---------------------------------------------------------------------------
// launch
// ---------------------------------------------------------------------------
extern "C" void kernel_launch(void* const* d_in, const int* in_sizes, int n_in,
                              void* d_out, int out_size) {
    const float* x  = (const float*)d_in[0];
    const float* Wq = (const float*)d_in[1];
    const float* Wk = (const float*)d_in[2];
    const float* Wv = (const float*)d_in[3];
    const float* Wp = (const float*)d_in[4];
    float* out = (float*)d_out;

    void *pxh, *pxl, *pqh, *pql, *prh, *prl, *psh, *psl, *pkh, *pkl, *pv, *psc, *pwh, *pwl;
    cudaGetSymbolAddress(&pxh, g_xh); cudaGetSymbolAddress(&pxl, g_xl);
    cudaGetSymbolAddress(&pqh, g_qh); cudaGetSymbolAddress(&pql, g_ql);
    cudaGetSymbolAddress(&prh, g_rh); cudaGetSymbolAddress(&prl, g_rl);
    cudaGetSymbolAddress(&psh, g_sh); cudaGetSymbolAddress(&psl, g_sl);
    cudaGetSymbolAddress(&pkh, g_kh); cudaGetSymbolAddress(&pkl, g_kl);
    cudaGetSymbolAddress(&pv, g_v);   cudaGetSymbolAddress(&psc, g_scores);
    cudaGetSymbolAddress(&pwh, g_wh); cudaGetSymbolAddress(&pwl, g_wl);

    __nv_bfloat16* xh = (__nv_bfloat16*)pxh; __nv_bfloat16* xl = (__nv_bfloat16*)pxl;
    __nv_bfloat16* qh = (__nv_bfloat16*)pqh; __nv_bfloat16* ql = (__nv_bfloat16*)pql;
    __nv_bfloat16* rh = (__nv_bfloat16*)prh; __nv_bfloat16* rl = (__nv_bfloat16*)prl;
    __nv_bfloat16* sh = (__nv_bfloat16*)psh; __nv_bfloat16* sl = (__nv_bfloat16*)psl;
    __nv_bfloat16* kh = (__nv_bfloat16*)pkh; __nv_bfloat16* kl = (__nv_bfloat16*)pkl;
    float* v = (float*)pv; float* scores = (float*)psc;
    __nv_bfloat16* wh = (__nv_bfloat16*)pwh; __nv_bfloat16* wl = (__nv_bfloat16*)pwl;

    cudaFuncSetAttribute(gemm_mma, cudaFuncAttributeMaxDynamicSharedMemorySize, GEMM_SMEM);

    // 1) convert x and weights to hi/lo bf16
    {
        int n4 = BB * TT * CC / 4;
        cvt_hilo<<<(n4 + 255) / 256, 256>>>((const float4*)x, (uint2*)xh, (uint2*)xl, n4);
        int w4 = CC * CC / 4;
        cvt_hilo<<<(w4 + 255) / 256, 256>>>((const float4*)Wq, (uint2*)(wh + 0 * CC * CC), (uint2*)(wl + 0 * CC * CC), w4);
        cvt_hilo<<<(w4 + 255) / 256, 256>>>((const float4*)Wk, (uint2*)(wh + 1 * CC * CC), (uint2*)(wl + 1 * CC * CC), w4);
        cvt_hilo<<<(w4 + 255) / 256, 256>>>((const float4*)Wv, (uint2*)(wh + 2 * CC * CC), (uint2*)(wl + 2 * CC * CC), w4);
        cvt_hilo<<<(w4 + 255) / 256, 256>>>((const float4*)Wp, (uint2*)(wh + 3 * CC * CC), (uint2*)(wl + 3 * CC * CC), w4);
    }

    // 2) pool x -> slots hi/lo
    pool_kernel<<<(BB * SS * CC) / 256, 256>>>(x);

    // 3) fused k (z=0, hi/lo) + v (z=1, fp32) projections: B = Wk/Wv via z stride
    {
        dim3 grid(CC / 256, (BB * SS) / 128, 2);
        gemm_mma<<<grid, 256, GEMM_SMEM>>>(sh, sl, wh + 1 * CC * CC, wl + 1 * CC * CC,
                                           v, kh, kl, BB * SS, CC, CC,
                                           0, (long long)CC * CC, 0, 1.0f, 2);
    }

    // 4) q = x @ Wq^T (hi/lo out)
    {
        dim3 grid(CC / 256, (BB * TT) / 128, 1);
        gemm_mma<<<grid, 256, GEMM_SMEM>>>(xh, xl, wh + 0 * CC * CC, wl + 0 * CC * CC,
                                           nullptr, qh, ql, BB * TT, CC, CC, 0, 0, 0, 1.0f, 1);
    }

    // 5) scores[b] = q[b] @ k[b]^T / 32 (batched, fp32 out)
    {
        dim3 grid(SS / 256, TT / 128, BB);
        gemm_mma<<<grid, 256, GEMM_SMEM>>>(qh, ql, kh, kl, scores, nullptr, nullptr,
                                           TT, SS, CC,
                                           (long long)TT * CC, (long long)SS * CC, (long long)TT * SS,
                                           0.03125f, 0);
    }

    // 6) top-8 + softmax + gather -> ret hi/lo
    topk_gather_kernel<<<(BB * TT) / 8, 256>>>();

    // 7) out = ret @ Wp^T * 0.5 (fp32 out)
    {
        dim3 grid(CC / 256, (BB * TT) / 128, 1);
        gemm_mma<<<grid, 256, GEMM_SMEM>>>(rh, rl, wh + 3 * CC * CC, wl + 3 * CC * CC,
                                           out, nullptr, nullptr, BB * TT, CC, CC, 0, 0, 0, 0.5f, 0);
    }
}

// round 10
// speedup vs baseline: 7.0962x; 3.4010x over previous
#include <cuda_runtime.h>
#include <cuda_fp16.h>
#include <math_constants.h>
#include <cstdint>

#define BB 8
#define TT 2048
#define CC 1024
#define SS 256
#define KTOP 8

// ---------------------------------------------------------------------------
// helpers
// ---------------------------------------------------------------------------
__device__ __forceinline__ uint32_t smem_u32(const void* p) {
    uint32_t a;
    asm("{ .reg .u64 t; cvta.to.shared.u64 t, %1; cvt.u32.u64 %0, t; }" : "=r"(a) : "l"(p));
    return a;
}
__device__ __forceinline__ uint32_t pack_h2(float a, float b) {
    __half2 h = __floats2half2_rn(a, b);
    return *reinterpret_cast<uint32_t*>(&h);
}
__device__ __forceinline__ float2 unpack_h2(uint32_t u) {
    __half2 h = *reinterpret_cast<__half2*>(&u);
    return __half22float2(h);
}
__device__ __forceinline__ void mma_f16(float* d, const uint32_t* a, const uint32_t* b) {
    asm volatile(
        "mma.sync.aligned.m16n8k16.row.col.f32.f16.f16.f32 "
        "{%0,%1,%2,%3}, {%4,%5,%6,%7}, {%8,%9}, {%0,%1,%2,%3};"
        : "+f"(d[0]), "+f"(d[1]), "+f"(d[2]), "+f"(d[3])
        : "r"(a[0]), "r"(a[1]), "r"(a[2]), "r"(a[3]), "r"(b[0]), "r"(b[1]));
}
__device__ __forceinline__ void ldsm_x4(uint32_t* r, uint32_t addr) {
    asm volatile("ldmatrix.sync.aligned.m8n8.x4.shared.b16 {%0,%1,%2,%3}, [%4];"
        : "=r"(r[0]), "=r"(r[1]), "=r"(r[2]), "=r"(r[3]) : "r"(addr));
}
__device__ __forceinline__ void ldsm_x2(uint32_t* r, uint32_t addr) {
    asm volatile("ldmatrix.sync.aligned.m8n8.x2.shared.b16 {%0,%1}, [%2];"
        : "=r"(r[0]), "=r"(r[1]) : "r"(addr));
}
__device__ __forceinline__ void cp16(uint32_t saddr, const void* gaddr) {
    asm volatile("cp.async.cg.shared.global [%0], [%1], 16;" :: "r"(saddr), "l"(gaddr));
}
// swizzled byte offset within a tile region: row (64B pitch), 16B unit u (0..3)
__device__ __forceinline__ uint32_t swz(int row, int u) {
    return (uint32_t)(row * 64 + ((u ^ ((row >> 1) & 3)) << 4));
}

#define WSCALE 32.0f            // weight pre-scale (power of 2; exact)

// ---------------------------------------------------------------------------
// scratch
// ---------------------------------------------------------------------------
__device__ __half g_xh[BB * TT * CC];
__device__ __half g_xl[BB * TT * CC];
__device__ __half g_sh[BB * SS * CC];
__device__ __half g_sl[BB * SS * CC];
__device__ __half g_kqh[BB * SS * CC];      // kq' = slots @ G'^T (scaled by 1024)
__device__ __half g_kql[BB * SS * CC];
__device__ float  g_pv[BB * SS * CC];       // pv (true scale)
__device__ float  g_scores[BB * TT * SS];
// A-buffer for weight products: slot0 = 32*Wq^T, slot1 = 32*Wp
__device__ __half g_wah[2 * CC * CC];
__device__ __half g_wal[2 * CC * CC];
// B-buffer: slot0 = 32*Wk^T, slot1 = 32*Wv^T
__device__ __half g_wbh[2 * CC * CC];
__device__ __half g_wbl[2 * CC * CC];
// products: slot0 = G' = 1024*Wq^T·Wk, slot1 = H' = 1024*Wp·Wv
__device__ __half g_wgh[2 * CC * CC];
__device__ __half g_wgl[2 * CC * CC];

// ---------------------------------------------------------------------------
// fp32 -> fp16 hi/lo (with optional scale)
// ---------------------------------------------------------------------------
__global__ void cvt_hilo(const float4* __restrict__ in, uint2* __restrict__ hi,
                         uint2* __restrict__ lo, int n4, float scale) {
    int i = blockIdx.x * 256 + threadIdx.x;
    if (i >= n4) return;
    float4 f = in[i];
    f.x *= scale; f.y *= scale; f.z *= scale; f.w *= scale;
    uint32_t h0 = pack_h2(f.x, f.y);
    uint32_t h1 = pack_h2(f.z, f.w);
    float2 e0 = unpack_h2(h0), e1 = unpack_h2(h1);
    hi[i] = make_uint2(h0, h1);
    lo[i] = make_uint2(pack_h2(f.x - e0.x, f.y - e0.y), pack_h2(f.z - e1.x, f.w - e1.y));
}

// ---------------------------------------------------------------------------
// transpose + scale + split: out^T (hi/lo fp16) of fp32 [CC,CC] matrix
// ---------------------------------------------------------------------------
__global__ void transpose_split(const float* __restrict__ in,
                                __half* __restrict__ oh, __half* __restrict__ ol) {
    __shared__ float t[32][33];
    const int bx = blockIdx.x * 32, by = blockIdx.y * 32;
    const int tx = threadIdx.x, ty = threadIdx.y;   // (32, 8)
#pragma unroll
    for (int j = 0; j < 4; j++)
        t[ty * 4 + j][tx] = in[(size_t)(by + ty * 4 + j) * CC + bx + tx];
    __syncthreads();
#pragma unroll
    for (int j = 0; j < 4; j++) {
        float v = t[tx][ty * 4 + j] * WSCALE;
        __half h = __float2half_rn(v);
        size_t o = (size_t)(bx + ty * 4 + j) * CC + by + tx;
        oh[o] = h;
        ol[o] = __float2half_rn(v - __half2float(h));
    }
}

// ---------------------------------------------------------------------------
// pooling -> slots hi/lo (unscaled)
// ---------------------------------------------------------------------------
__global__ void pool_kernel(const float* __restrict__ x) {
    int i = blockIdx.x * 256 + threadIdx.x;
    int c = i & (CC - 1);
    int bs = i >> 10;
    int s = bs & (SS - 1);
    int b = bs >> 8;
    const float* p = x + ((long)b * TT + (long)s * 8) * CC + c;
    float sum = 0.f;
#pragma unroll
    for (int u = 0; u < 8; u++) sum += p[(long)u * CC];
    sum *= 0.125f;
    __half h = __float2half_rn(sum);
    g_sh[i] = h;
    g_sl[i] = __float2half_rn(sum - __half2float(h));
}

// ---------------------------------------------------------------------------
// Pipelined split-fp16 HMMA GEMM, CTA 128x128, BK=32, 8 warps (2m x 4n),
// warp tile 64x32. 3-stage cp.async; stage = [Ah 8K][Al 8K][Bh 8K][Bl 8K]=32KB.
// C[m,n] = a * sum_k (Ah+Al)[m,k]*(Bh+Bl)[n,k]   (AhBh + AhBl + AlBh)
// mode 0: fp32 out (alpha). mode 1: fp16 hi/lo out (alpha).
// mode 2: z=0 hi/lo out (alpha), z=1 fp32 out (alpha2); cbase 0 for both.
// ---------------------------------------------------------------------------
#define STAGES 3
#define STAGE_BYTES 32768
#define GEMM_SMEM (STAGES * STAGE_BYTES)

__global__ __launch_bounds__(256)
void gemm_mma(const __half* __restrict__ Ah, const __half* __restrict__ Al,
              const __half* __restrict__ Bh, const __half* __restrict__ Bl,
              float* __restrict__ Cf, __half* __restrict__ Chi, __half* __restrict__ Clo,
              int M, int N, int K,
              long long sA, long long sB, long long sC,
              float alpha, float alpha2, int mode) {
    extern __shared__ __align__(16) char smem[];
    const uint32_t sb = smem_u32(smem);

    const int tid = threadIdx.x;
    const int wid = tid >> 5;
    const int lane = tid & 31;
    const int bz = blockIdx.z;
    const size_t m0 = (size_t)blockIdx.y * 128;
    const size_t n0 = (size_t)blockIdx.x * 128;

    const __half* gAh = Ah + (size_t)bz * (size_t)sA;
    const __half* gAl = Al + (size_t)bz * (size_t)sA;
    const __half* gBh = Bh + (size_t)bz * (size_t)sB;
    const __half* gBl = Bl + (size_t)bz * (size_t)sB;

    const int lrow = tid >> 1;
    const int lu   = (tid & 1) * 2;
    const size_t aoffg = (m0 + lrow) * (size_t)K;
    const size_t boffg = (n0 + lrow) * (size_t)K;

    const int nch = K >> 5;

#define LOAD_STAGE(stg) do { \
    const uint32_t st = sb + ((stg) % STAGES) * STAGE_BYTES; \
    const int kof = (stg) * 32; \
    _Pragma("unroll") \
    for (int j = 0; j < 2; j++) { \
        int u = lu + j; \
        uint32_t so = swz(lrow, u); \
        size_t goa = aoffg + kof + u * 8; \
        size_t gob = boffg + kof + u * 8; \
        cp16(st + so,         gAh + goa); \
        cp16(st + 8192 + so,  gAl + goa); \
        cp16(st + 16384 + so, gBh + gob); \
        cp16(st + 24576 + so, gBl + gob); \
    } \
} while (0)

    const int wm = wid >> 2;
    const int wn = wid & 3;

    float acc[4][4][4];
#pragma unroll
    for (int i = 0; i < 4; i++)
#pragma unroll
        for (int j = 0; j < 4; j++)
#pragma unroll
            for (int r = 0; r < 4; r++) acc[i][j][r] = 0.f;

#pragma unroll
    for (int s = 0; s < STAGES - 1; s++) {
        if (s < nch) LOAD_STAGE(s);
        asm volatile("cp.async.commit_group;" ::: "memory");
    }

    for (int c = 0; c < nch; c++) {
        asm volatile("cp.async.wait_group %0;" :: "n"(STAGES - 2) : "memory");
        __syncthreads();

        if (c + STAGES - 1 < nch) LOAD_STAGE(c + STAGES - 1);
        asm volatile("cp.async.commit_group;" ::: "memory");

        const uint32_t st = sb + (c % STAGES) * STAGE_BYTES;
#pragma unroll
        for (int ks = 0; ks < 2; ks++) {
            uint32_t bhf[4][2], blf[4][2];
            const int rB0 = wn * 32 + (lane & 7);
            const int cuB = 2 * ks + ((lane >> 3) & 1);
#pragma unroll
            for (int fn = 0; fn < 4; fn++) {
                uint32_t ad = st + 16384 + swz(rB0 + 8 * fn, cuB);
                ldsm_x2(bhf[fn], ad);
                ldsm_x2(blf[fn], ad + 8192);
            }
#pragma unroll
            for (int fm = 0; fm < 4; fm++) {
                int rowA = wm * 64 + fm * 16 + (lane & 7) + ((lane >> 3) & 1) * 8;
                int cuA = 2 * ks + (lane >> 4);
                uint32_t ad = st + swz(rowA, cuA);
                uint32_t ah[4], al[4];
                ldsm_x4(ah, ad);
                ldsm_x4(al, ad + 8192);
#pragma unroll
                for (int fn = 0; fn < 4; fn++) mma_f16(acc[fm][fn], ah, bhf[fn]);
#pragma unroll
                for (int fn = 0; fn < 4; fn++) mma_f16(acc[fm][fn], ah, blf[fn]);
#pragma unroll
                for (int fn = 0; fn < 4; fn++) mma_f16(acc[fm][fn], al, bhf[fn]);
            }
        }
    }
#undef LOAD_STAGE

    // ---- epilogue ----
    int emode = mode;
    float a = alpha;
    if (mode == 2) { emode = (bz == 0) ? 1 : 0; if (bz == 1) a = alpha2; }
    const size_t cbase = (mode == 2) ? 0 : (size_t)bz * (size_t)sC;
    const int eg = lane >> 2;
    const int et = lane & 3;

#pragma unroll
    for (int fm = 0; fm < 4; fm++) {
        size_t row0 = m0 + wm * 64 + fm * 16 + eg;
#pragma unroll
        for (int fn = 0; fn < 4; fn++) {
            size_t col = n0 + wn * 32 + fn * 8 + et * 2;
            float c0 = a * acc[fm][fn][0];
            float c1 = a * acc[fm][fn][1];
            float c2 = a * acc[fm][fn][2];
            float c3 = a * acc[fm][fn][3];
            if (emode == 0) {
                *(float2*)(Cf + cbase + row0 * N + col)       = make_float2(c0, c1);
                *(float2*)(Cf + cbase + (row0 + 8) * N + col) = make_float2(c2, c3);
            } else {
                uint32_t h0 = pack_h2(c0, c1);
                float2 e0 = unpack_h2(h0);
                uint32_t l0 = pack_h2(c0 - e0.x, c1 - e0.y);
                uint32_t h1 = pack_h2(c2, c3);
                float2 e1 = unpack_h2(h1);
                uint32_t l1 = pack_h2(c2 - e1.x, c3 - e1.y);
                *(uint32_t*)(Chi + cbase + row0 * N + col)       = h0;
                *(uint32_t*)(Clo + cbase + row0 * N + col)       = l0;
                *(uint32_t*)(Chi + cbase + (row0 + 8) * N + col) = h1;
                *(uint32_t*)(Clo + cbase + (row0 + 8) * N + col) = l1;
            }
        }
    }
}

// ---------------------------------------------------------------------------
// top-8 + softmax + weighted PV gather; writes final output (x0.5 folded in)
// ---------------------------------------------------------------------------
__global__ void topk_gather_kernel(float* __restrict__ out) {
    const int warp_global = (blockIdx.x * blockDim.x + threadIdx.x) >> 5;
    const int lane = threadIdx.x & 31;
    const int b = warp_global >> 11;
    const int t = warp_global & (TT - 1);

    const float* srow = g_scores + ((long)b * TT + t) * SS;

    float vals[8];
#pragma unroll
    for (int i = 0; i < 8; i++) vals[i] = srow[lane + 32 * i];

    float w[KTOP];
    int   idx[KTOP];

#pragma unroll
    for (int r = 0; r < KTOP; r++) {
        float best = -CUDART_INF_F;
        int   bi = 0x7fffffff;
#pragma unroll
        for (int i = 0; i < 8; i++)
            if (vals[i] > best) { best = vals[i]; bi = lane + 32 * i; }
#pragma unroll
        for (int off = 16; off; off >>= 1) {
            float ov = __shfl_xor_sync(0xffffffffu, best, off);
            int   oi = __shfl_xor_sync(0xffffffffu, bi, off);
            if (ov > best || (ov == best && oi < bi)) { best = ov; bi = oi; }
        }
        w[r] = best;
        idx[r] = bi;
#pragma unroll
        for (int i = 0; i < 8; i++)
            if ((lane + 32 * i) == bi) vals[i] = -CUDART_INF_F;
    }

    float mx = w[0];
    float sum = 0.f;
#pragma unroll
    for (int r = 0; r < KTOP; r++) { w[r] = __expf(w[r] - mx); sum += w[r]; }
    float inv = 0.5f / sum;                         // RETRIEVAL_WEIGHT folded in
#pragma unroll
    for (int r = 0; r < KTOP; r++) w[r] *= inv;

    const float* pvb = g_pv + (long)b * SS * CC;
    float* o = out + ((long)b * TT + t) * CC;
#pragma unroll
    for (int it = 0; it < CC / 128; it++) {
        int c = lane * 4 + it * 128;
        float4 acc = make_float4(0.f, 0.f, 0.f, 0.f);
#pragma unroll
        for (int r = 0; r < KTOP; r++) {
            float4 vv = *(const float4*)(pvb + (long)idx[r] * CC + c);
            acc.x = fmaf(w[r], vv.x, acc.x);
            acc.y = fmaf(w[r], vv.y, acc.y);
            acc.z = fmaf(w[r], vv.z, acc.z);
            acc.w = fmaf(w[r], vv.w, acc.w);
        }
        *(float4*)(o + c) = acc;
    }
}

// ---------------------------------------------------------------------------
// launch
// ---------------------------------------------------------------------------
extern "C" void kernel_launch(void* const* d_in, const int* in_sizes, int n_in,
                              void* d_out, int out_size) {
    const float* x  = (const float*)d_in[0];
    const float* Wq = (const float*)d_in[1];
    const float* Wk = (const float*)d_in[2];
    const float* Wv = (const float*)d_in[3];
    const float* Wp = (const float*)d_in[4];
    float* out = (float*)d_out;

    void *pxh, *pxl, *psh, *psl, *pkqh, *pkql, *ppv, *psc;
    void *pwah, *pwal, *pwbh, *pwbl, *pwgh, *pwgl;
    cudaGetSymbolAddress(&pxh, g_xh);  cudaGetSymbolAddress(&pxl, g_xl);
    cudaGetSymbolAddress(&psh, g_sh);  cudaGetSymbolAddress(&psl, g_sl);
    cudaGetSymbolAddress(&pkqh, g_kqh); cudaGetSymbolAddress(&pkql, g_kql);
    cudaGetSymbolAddress(&ppv, g_pv);  cudaGetSymbolAddress(&psc, g_scores);
    cudaGetSymbolAddress(&pwah, g_wah); cudaGetSymbolAddress(&pwal, g_wal);
    cudaGetSymbolAddress(&pwbh, g_wbh); cudaGetSymbolAddress(&pwbl, g_wbl);
    cudaGetSymbolAddress(&pwgh, g_wgh); cudaGetSymbolAddress(&pwgl, g_wgl);

    __half* xh = (__half*)pxh;  __half* xl = (__half*)pxl;
    __half* sh = (__half*)psh;  __half* sl = (__half*)psl;
    __half* kqh = (__half*)pkqh; __half* kql = (__half*)pkql;
    float* pv = (float*)ppv; float* scores = (float*)psc;
    __half* wah = (__half*)pwah; __half* wal = (__half*)pwal;
    __half* wbh = (__half*)pwbh; __half* wbl = (__half*)pwbl;
    __half* wgh = (__half*)pwgh; __half* wgl = (__half*)pwgl;

    cudaFuncSetAttribute(gemm_mma, cudaFuncAttributeMaxDynamicSharedMemorySize, GEMM_SMEM);

    const long long CC2 = (long long)CC * CC;

    // 1) conversions / transposes (weights pre-scaled by 32)
    {
        int n4 = BB * TT * CC / 4;
        cvt_hilo<<<n4 / 256, 256>>>((const float4*)x, (uint2*)xh, (uint2*)xl, n4, 1.0f);
        dim3 tg(CC / 32, CC / 32), tb(32, 8);
        // A-buffer: slot0 = 32*Wq^T, slot1 = 32*Wp
        transpose_split<<<tg, tb>>>(Wq, wah, wal);
        int w4 = CC * CC / 4;
        cvt_hilo<<<w4 / 256, 256>>>((const float4*)Wp, (uint2*)(wah + CC2), (uint2*)(wal + CC2), w4, WSCALE);
        // B-buffer: slot0 = 32*Wk^T, slot1 = 32*Wv^T
        transpose_split<<<tg, tb>>>(Wk, wbh, wbl);
        transpose_split<<<tg, tb>>>(Wv, wbh + CC2, wbl + CC2);
    }

    // 2) pool x -> slots hi/lo
    pool_kernel<<<(BB * SS * CC) / 256, 256>>>(x);

    // 3) weight products (batched z=2), hi/lo out, alpha=1 (keep x1024 scale):
    //    z=0: G' = (32Wq)^T·(32Wk)   z=1: H' = (32Wp)·(32Wv)
    {
        dim3 grid(CC / 128, CC / 128, 2);
        gemm_mma<<<grid, 256, GEMM_SMEM>>>(wah, wal, wbh, wbl,
                                           nullptr, wgh, wgl, CC, CC, CC,
                                           CC2, CC2, CC2, 1.0f, 0.f, 1);
    }

    // 4) kq' + pv (batched z=2, mode 2):
    //    z=0: kq' = TN(slots, G') -> hi/lo, alpha=1 (scaled by 1024)
    //    z=1: pv  = TN(slots, H')·(1/1024) -> fp32 (true scale)
    {
        dim3 grid(CC / 128, (BB * SS) / 128, 2);
        gemm_mma<<<grid, 256, GEMM_SMEM>>>(sh, sl, wgh, wgl,
                                           pv, kqh, kql, BB * SS, CC, CC,
                                           0, CC2, 0, 1.0f, 1.0f / 1024.0f, 2);
    }

    // 5) scores[b] = x[b] @ kq'[b]^T / (32*1024)  (batched over B, fp32)
    {
        dim3 grid(SS / 128, TT / 128, BB);
        gemm_mma<<<grid, 256, GEMM_SMEM>>>(xh, xl, kqh, kql, scores, nullptr, nullptr,
                                           TT, SS, CC,
                                           (long long)TT * CC, (long long)SS * CC, (long long)TT * SS,
                                           1.0f / 32768.0f, 0.f, 0);
    }

    // 6) top-8 + softmax + gather of pv -> out (0.5 folded in)
    topk_gather_kernel<<<(BB * TT) / 8, 256>>>(out);
}

// round 12
// speedup vs baseline: 7.7741x; 1.0955x over previous
#include <cuda_runtime.h>
#include <cuda_fp16.h>
#include <math_constants.h>
#include <cstdint>

#define BB 8
#define TT 2048
#define CC 1024
#define SS 256
#define KTOP 8

// ---------------------------------------------------------------------------
// helpers
// ---------------------------------------------------------------------------
__device__ __forceinline__ uint32_t smem_u32(const void* p) {
    uint32_t a;
    asm("{ .reg .u64 t; cvta.to.shared.u64 t, %1; cvt.u32.u64 %0, t; }" : "=r"(a) : "l"(p));
    return a;
}
__device__ __forceinline__ uint32_t pack_h2(float a, float b) {
    __half2 h = __floats2half2_rn(a, b);
    return *reinterpret_cast<uint32_t*>(&h);
}
__device__ __forceinline__ float2 unpack_h2(uint32_t u) {
    __half2 h = *reinterpret_cast<__half2*>(&u);
    return __half22float2(h);
}
__device__ __forceinline__ void mma_f16(float* d, const uint32_t* a, const uint32_t* b) {
    asm volatile(
        "mma.sync.aligned.m16n8k16.row.col.f32.f16.f16.f32 "
        "{%0,%1,%2,%3}, {%4,%5,%6,%7}, {%8,%9}, {%0,%1,%2,%3};"
        : "+f"(d[0]), "+f"(d[1]), "+f"(d[2]), "+f"(d[3])
        : "r"(a[0]), "r"(a[1]), "r"(a[2]), "r"(a[3]), "r"(b[0]), "r"(b[1]));
}
__device__ __forceinline__ void ldsm_x4(uint32_t* r, uint32_t addr) {
    asm volatile("ldmatrix.sync.aligned.m8n8.x4.shared.b16 {%0,%1,%2,%3}, [%4];"
        : "=r"(r[0]), "=r"(r[1]), "=r"(r[2]), "=r"(r[3]) : "r"(addr));
}
__device__ __forceinline__ void ldsm_x2(uint32_t* r, uint32_t addr) {
    asm volatile("ldmatrix.sync.aligned.m8n8.x2.shared.b16 {%0,%1}, [%2];"
        : "=r"(r[0]), "=r"(r[1]) : "r"(addr));
}
__device__ __forceinline__ void cp16(uint32_t saddr, const void* gaddr) {
    asm volatile("cp.async.cg.shared.global [%0], [%1], 16;" :: "r"(saddr), "l"(gaddr));
}
// swizzled byte offset within a tile region: row (64B pitch), 16B unit u (0..3)
__device__ __forceinline__ uint32_t swz(int row, int u) {
    return (uint32_t)(row * 64 + ((u ^ ((row >> 1) & 3)) << 4));
}

#define WSCALE 32.0f            // weight pre-scale (power of 2; exact)

// ---------------------------------------------------------------------------
// scratch
// ---------------------------------------------------------------------------
__device__ __half g_xh[BB * TT * CC];
__device__ __half g_xl[BB * TT * CC];
__device__ __half g_sh[BB * SS * CC];
__device__ __half g_sl[BB * SS * CC];
__device__ __half g_kqh[BB * SS * CC];      // kq' (scaled by 1024)
__device__ __half g_kql[BB * SS * CC];
__device__ float  g_pv[BB * SS * CC];       // pv (true scale)
__device__ float  g_scores[BB * TT * SS];
// A-buffer for weight products: slot0 = 32*Wq^T, slot1 = 32*Wp
__device__ __half g_wah[2 * CC * CC];
__device__ __half g_wal[2 * CC * CC];
// B-buffer: slot0 = 32*Wk^T, slot1 = 32*Wv^T
__device__ __half g_wbh[2 * CC * CC];
__device__ __half g_wbl[2 * CC * CC];
// products: slot0 = G' = 1024*Wq^T·Wk, slot1 = H' = 1024*Wp·Wv
__device__ __half g_wgh[2 * CC * CC];
__device__ __half g_wgl[2 * CC * CC];

// ---------------------------------------------------------------------------
// fp32 -> fp16 hi/lo (with optional scale)
// ---------------------------------------------------------------------------
__global__ void cvt_hilo(const float4* __restrict__ in, uint2* __restrict__ hi,
                         uint2* __restrict__ lo, int n4, float scale) {
    int i = blockIdx.x * 256 + threadIdx.x;
    if (i >= n4) return;
    float4 f = in[i];
    f.x *= scale; f.y *= scale; f.z *= scale; f.w *= scale;
    uint32_t h0 = pack_h2(f.x, f.y);
    uint32_t h1 = pack_h2(f.z, f.w);
    float2 e0 = unpack_h2(h0), e1 = unpack_h2(h1);
    hi[i] = make_uint2(h0, h1);
    lo[i] = make_uint2(pack_h2(f.x - e0.x, f.y - e0.y), pack_h2(f.z - e1.x, f.w - e1.y));
}

// ---------------------------------------------------------------------------
// fused: x -> xh/xl AND slots (mean of 8 rows) -> sh/sl. One read of x.
// thread i = (b, s, c); covers timesteps u = 0..7 of that slot.
// ---------------------------------------------------------------------------
__global__ void pool_cvt_kernel(const float* __restrict__ x) {
    int i = blockIdx.x * 256 + threadIdx.x;     // [0, BB*SS*CC)
    int c = i & (CC - 1);
    int bs = i >> 10;
    int s = bs & (SS - 1);
    int b = bs >> 8;
    const size_t base = ((size_t)b * TT + (size_t)s * 8) * CC + c;
    float sum = 0.f;
#pragma unroll
    for (int u = 0; u < 8; u++) {
        float v = x[base + (size_t)u * CC];
        sum += v;
        __half h = __float2half_rn(v);
        g_xh[base + (size_t)u * CC] = h;
        g_xl[base + (size_t)u * CC] = __float2half_rn(v - __half2float(h));
    }
    sum *= 0.125f;
    __half h = __float2half_rn(sum);
    g_sh[i] = h;
    g_sl[i] = __float2half_rn(sum - __half2float(h));
}

// ---------------------------------------------------------------------------
// batched transpose + scale + split (z selects which weight)
// z=0: Wq -> wah/wal slot0;  z=1: Wk -> wbh/wbl slot0;  z=2: Wv -> wbh/wbl slot1
// ---------------------------------------------------------------------------
__global__ void transpose3_split(const float* __restrict__ w0, const float* __restrict__ w1,
                                 const float* __restrict__ w2) {
    __shared__ float t[32][33];
    const int z = blockIdx.z;
    const float* in = (z == 0) ? w0 : (z == 1) ? w1 : w2;
    __half* oh = (z == 0) ? g_wah : (z == 1) ? g_wbh : (g_wbh + (size_t)CC * CC);
    __half* ol = (z == 0) ? g_wal : (z == 1) ? g_wbl : (g_wbl + (size_t)CC * CC);

    const int bx = blockIdx.x * 32, by = blockIdx.y * 32;
    const int tx = threadIdx.x, ty = threadIdx.y;   // (32, 8)
#pragma unroll
    for (int j = 0; j < 4; j++)
        t[ty * 4 + j][tx] = in[(size_t)(by + ty * 4 + j) * CC + bx + tx];
    __syncthreads();
#pragma unroll
    for (int j = 0; j < 4; j++) {
        float v = t[tx][ty * 4 + j] * WSCALE;
        __half h = __float2half_rn(v);
        size_t o = (size_t)(bx + ty * 4 + j) * CC + by + tx;
        oh[o] = h;
        ol[o] = __float2half_rn(v - __half2float(h));
    }
}

// ---------------------------------------------------------------------------
// Pipelined split-fp16 HMMA GEMM, CTA 128x128, BK=32, 8 warps (2m x 4n),
// warp tile 64x32. 2-stage cp.async (32KB/stage, 64KB total -> 2 CTAs/SM).
// C[m,n] = a * sum_k (Ah+Al)[m,k]*(Bh+Bl)[n,k]
//   full:     AhBh + AhBl + AlBh
//   reduced:  AhBh + AlBh           (mode 2, z=1 only: pv path)
// mode 0: fp32 out (alpha). mode 1: fp16 hi/lo out (alpha).
// mode 2: z=0 hi/lo out (alpha, full), z=1 fp32 out (alpha2, reduced); cbase 0.
// ---------------------------------------------------------------------------
#define STAGES 2
#define STAGE_BYTES 32768
#define GEMM_SMEM (STAGES * STAGE_BYTES)

__global__ __launch_bounds__(256, 2)
void gemm_mma(const __half* __restrict__ Ah, const __half* __restrict__ Al,
              const __half* __restrict__ Bh, const __half* __restrict__ Bl,
              float* __restrict__ Cf, __half* __restrict__ Chi, __half* __restrict__ Clo,
              int M, int N, int K,
              long long sA, long long sB, long long sC,
              float alpha, float alpha2, int mode) {
    extern __shared__ __align__(16) char smem[];
    const uint32_t sb = smem_u32(smem);

    const int tid = threadIdx.x;
    const int wid = tid >> 5;
    const int lane = tid & 31;
    const int bz = blockIdx.z;
    const size_t m0 = (size_t)blockIdx.y * 128;
    const size_t n0 = (size_t)blockIdx.x * 128;

    const bool full3 = !(mode == 2 && bz == 1);

    const __half* gAh = Ah + (size_t)bz * (size_t)sA;
    const __half* gAl = Al + (size_t)bz * (size_t)sA;
    const __half* gBh = Bh + (size_t)bz * (size_t)sB;
    const __half* gBl = Bl + (size_t)bz * (size_t)sB;

    const int lrow = tid >> 1;
    const int lu   = (tid & 1) * 2;
    const size_t aoffg = (m0 + lrow) * (size_t)K;
    const size_t boffg = (n0 + lrow) * (size_t)K;

    const int nch = K >> 5;

#define LOAD_STAGE(stg) do { \
    const uint32_t st = sb + ((stg) % STAGES) * STAGE_BYTES; \
    const int kof = (stg) * 32; \
    _Pragma("unroll") \
    for (int j = 0; j < 2; j++) { \
        int u = lu + j; \
        uint32_t so = swz(lrow, u); \
        size_t goa = aoffg + kof + u * 8; \
        size_t gob = boffg + kof + u * 8; \
        cp16(st + so,         gAh + goa); \
        cp16(st + 8192 + so,  gAl + goa); \
        cp16(st + 16384 + so, gBh + gob); \
        cp16(st + 24576 + so, gBl + gob); \
    } \
} while (0)

    const int wm = wid >> 2;
    const int wn = wid & 3;

    float acc[4][4][4];
#pragma unroll
    for (int i = 0; i < 4; i++)
#pragma unroll
        for (int j = 0; j < 4; j++)
#pragma unroll
            for (int r = 0; r < 4; r++) acc[i][j][r] = 0.f;

    // prologue: one stage in flight
    LOAD_STAGE(0);
    asm volatile("cp.async.commit_group;" ::: "memory");

    for (int c = 0; c < nch; c++) {
        asm volatile("cp.async.wait_group 0;" ::: "memory");
        __syncthreads();

        if (c + 1 < nch) LOAD_STAGE(c + 1);
        asm volatile("cp.async.commit_group;" ::: "memory");

        const uint32_t st = sb + (c % STAGES) * STAGE_BYTES;
#pragma unroll
        for (int ks = 0; ks < 2; ks++) {
            uint32_t bhf[4][2], blf[4][2];
            const int rB0 = wn * 32 + (lane & 7);
            const int cuB = 2 * ks + ((lane >> 3) & 1);
#pragma unroll
            for (int fn = 0; fn < 4; fn++) {
                uint32_t ad = st + 16384 + swz(rB0 + 8 * fn, cuB);
                ldsm_x2(bhf[fn], ad);
                ldsm_x2(blf[fn], ad + 8192);
            }
#pragma unroll
            for (int fm = 0; fm < 4; fm++) {
                int rowA = wm * 64 + fm * 16 + (lane & 7) + ((lane >> 3) & 1) * 8;
                int cuA = 2 * ks + (lane >> 4);
                uint32_t ad = st + swz(rowA, cuA);
                uint32_t ah[4], al[4];
                ldsm_x4(ah, ad);
                ldsm_x4(al, ad + 8192);
#pragma unroll
                for (int fn = 0; fn < 4; fn++) mma_f16(acc[fm][fn], ah, bhf[fn]);
                if (full3) {
#pragma unroll
                    for (int fn = 0; fn < 4; fn++) mma_f16(acc[fm][fn], ah, blf[fn]);
                }
#pragma unroll
                for (int fn = 0; fn < 4; fn++) mma_f16(acc[fm][fn], al, bhf[fn]);
            }
        }
    }
#undef LOAD_STAGE

    // ---- epilogue ----
    int emode = mode;
    float a = alpha;
    if (mode == 2) { emode = (bz == 0) ? 1 : 0; if (bz == 1) a = alpha2; }
    const size_t cbase = (mode == 2) ? 0 : (size_t)bz * (size_t)sC;
    const int eg = lane >> 2;
    const int et = lane & 3;

#pragma unroll
    for (int fm = 0; fm < 4; fm++) {
        size_t row0 = m0 + wm * 64 + fm * 16 + eg;
#pragma unroll
        for (int fn = 0; fn < 4; fn++) {
            size_t col = n0 + wn * 32 + fn * 8 + et * 2;
            float c0 = a * acc[fm][fn][0];
            float c1 = a * acc[fm][fn][1];
            float c2 = a * acc[fm][fn][2];
            float c3 = a * acc[fm][fn][3];
            if (emode == 0) {
                *(float2*)(Cf + cbase + row0 * N + col)       = make_float2(c0, c1);
                *(float2*)(Cf + cbase + (row0 + 8) * N + col) = make_float2(c2, c3);
            } else {
                uint32_t h0 = pack_h2(c0, c1);
                float2 e0 = unpack_h2(h0);
                uint32_t l0 = pack_h2(c0 - e0.x, c1 - e0.y);
                uint32_t h1 = pack_h2(c2, c3);
                float2 e1 = unpack_h2(h1);
                uint32_t l1 = pack_h2(c2 - e1.x, c3 - e1.y);
                *(uint32_t*)(Chi + cbase + row0 * N + col)       = h0;
                *(uint32_t*)(Clo + cbase + row0 * N + col)       = l0;
                *(uint32_t*)(Chi + cbase + (row0 + 8) * N + col) = h1;
                *(uint32_t*)(Clo + cbase + (row0 + 8) * N + col) = l1;
            }
        }
    }
}

// ---------------------------------------------------------------------------
// top-8 + softmax + weighted PV gather; writes final output (x0.5 folded in)
// ---------------------------------------------------------------------------
__global__ void topk_gather_kernel(float* __restrict__ out) {
    const int warp_global = (blockIdx.x * blockDim.x + threadIdx.x) >> 5;
    const int lane = threadIdx.x & 31;
    const int b = warp_global >> 11;
    const int t = warp_global & (TT - 1);

    const float* srow = g_scores + ((long)b * TT + t) * SS;

    float vals[8];
#pragma unroll
    for (int i = 0; i < 8; i++) vals[i] = srow[lane + 32 * i];

    float w[KTOP];
    int   idx[KTOP];

#pragma unroll
    for (int r = 0; r < KTOP; r++) {
        float best = -CUDART_INF_F;
        int   bi = 0x7fffffff;
#pragma unroll
        for (int i = 0; i < 8; i++)
            if (vals[i] > best) { best = vals[i]; bi = lane + 32 * i; }
#pragma unroll
        for (int off = 16; off; off >>= 1) {
            float ov = __shfl_xor_sync(0xffffffffu, best, off);
            int   oi = __shfl_xor_sync(0xffffffffu, bi, off);
            if (ov > best || (ov == best && oi < bi)) { best = ov; bi = oi; }
        }
        w[r] = best;
        idx[r] = bi;
#pragma unroll
        for (int i = 0; i < 8; i++)
            if ((lane + 32 * i) == bi) vals[i] = -CUDART_INF_F;
    }

    float mx = w[0];
    float sum = 0.f;
#pragma unroll
    for (int r = 0; r < KTOP; r++) { w[r] = __expf(w[r] - mx); sum += w[r]; }
    float inv = 0.5f / sum;                         // RETRIEVAL_WEIGHT folded in
#pragma unroll
    for (int r = 0; r < KTOP; r++) w[r] *= inv;

    const float* pvb = g_pv + (long)b * SS * CC;
    float* o = out + ((long)b * TT + t) * CC;
#pragma unroll
    for (int it = 0; it < CC / 128; it++) {
        int c = lane * 4 + it * 128;
        float4 acc = make_float4(0.f, 0.f, 0.f, 0.f);
#pragma unroll
        for (int r = 0; r < KTOP; r++) {
            float4 vv = *(const float4*)(pvb + (long)idx[r] * CC + c);
            acc.x = fmaf(w[r], vv.x, acc.x);
            acc.y = fmaf(w[r], vv.y, acc.y);
            acc.z = fmaf(w[r], vv.z, acc.z);
            acc.w = fmaf(w[r], vv.w, acc.w);
        }
        *(float4*)(o + c) = acc;
    }
}

// ---------------------------------------------------------------------------
// launch
// ---------------------------------------------------------------------------
extern "C" void kernel_launch(void* const* d_in, const int* in_sizes, int n_in,
                              void* d_out, int out_size) {
    const float* x  = (const float*)d_in[0];
    const float* Wq = (const float*)d_in[1];
    const float* Wk = (const float*)d_in[2];
    const float* Wv = (const float*)d_in[3];
    const float* Wp = (const float*)d_in[4];
    float* out = (float*)d_out;

    void *pxh, *pxl, *psh, *psl, *pkqh, *pkql, *ppv, *psc;
    void *pwah, *pwal, *pwbh, *pwbl, *pwgh, *pwgl;
    cudaGetSymbolAddress(&pxh, g_xh);  cudaGetSymbolAddress(&pxl, g_xl);
    cudaGetSymbolAddress(&psh, g_sh);  cudaGetSymbolAddress(&psl, g_sl);
    cudaGetSymbolAddress(&pkqh, g_kqh); cudaGetSymbolAddress(&pkql, g_kql);
    cudaGetSymbolAddress(&ppv, g_pv);  cudaGetSymbolAddress(&psc, g_scores);
    cudaGetSymbolAddress(&pwah, g_wah); cudaGetSymbolAddress(&pwal, g_wal);
    cudaGetSymbolAddress(&pwbh, g_wbh); cudaGetSymbolAddress(&pwbl, g_wbl);
    cudaGetSymbolAddress(&pwgh, g_wgh); cudaGetSymbolAddress(&pwgl, g_wgl);

    __half* xh = (__half*)pxh;  __half* xl = (__half*)pxl;
    __half* sh = (__half*)psh;  __half* sl = (__half*)psl;
    __half* kqh = (__half*)pkqh; __half* kql = (__half*)pkql;
    float* pv = (float*)ppv; float* scores = (float*)psc;
    __half* wah = (__half*)pwah; __half* wal = (__half*)pwal;
    __half* wbh = (__half*)pwbh; __half* wbl = (__half*)pwbl;
    __half* wgh = (__half*)pwgh; __half* wgl = (__half*)pwgl;

    cudaFuncSetAttribute(gemm_mma, cudaFuncAttributeMaxDynamicSharedMemorySize, GEMM_SMEM);

    const long long CC2 = (long long)CC * CC;

    // 1) fused pool + x conversion; batched weight transposes; Wp cvt
    pool_cvt_kernel<<<(BB * SS * CC) / 256, 256>>>(x);
    {
        dim3 tg(CC / 32, CC / 32, 3), tb(32, 8);
        transpose3_split<<<tg, tb>>>(Wq, Wk, Wv);
        int w4 = CC * CC / 4;
        cvt_hilo<<<w4 / 256, 256>>>((const float4*)Wp, (uint2*)(wah + CC2), (uint2*)(wal + CC2), w4, WSCALE);
    }

    // 2) weight products (batched z=2), hi/lo out, alpha=1 (keep x1024 scale):
    //    z=0: G' = (32Wq)^T·(32Wk)   z=1: H' = (32Wp)·(32Wv)
    {
        dim3 grid(CC / 128, CC / 128, 2);
        gemm_mma<<<grid, 256, GEMM_SMEM>>>(wah, wal, wbh, wbl,
                                           nullptr, wgh, wgl, CC, CC, CC,
                                           CC2, CC2, CC2, 1.0f, 0.f, 1);
    }

    // 3) kq' + pv (batched z=2, mode 2):
    //    z=0: kq' = TN(slots, G') -> hi/lo, full 3-product (scores chain)
    //    z=1: pv  = TN(slots, H')·(1/1024) -> fp32, reduced 2-product
    {
        dim3 grid(CC / 128, (BB * SS) / 128, 2);
        gemm_mma<<<grid, 256, GEMM_SMEM>>>(sh, sl, wgh, wgl,
                                           pv, kqh, kql, BB * SS, CC, CC,
                                           0, CC2, 0, 1.0f, 1.0f / 1024.0f, 2);
    }

    // 4) scores[b] = x[b] @ kq'[b]^T / (32*1024)  (batched over B, fp32)
    {
        dim3 grid(SS / 128, TT / 128, BB);
        gemm_mma<<<grid, 256, GEMM_SMEM>>>(xh, xl, kqh, kql, scores, nullptr, nullptr,
                                           TT, SS, CC,
                                           (long long)TT * CC, (long long)SS * CC, (long long)TT * SS,
                                           1.0f / 32768.0f, 0.f, 0);
    }

    // 5) top-8 + softmax + gather of pv -> out (0.5 folded in)
    topk_gather_kernel<<<(BB * TT) / 8, 256>>>(out);
}